// round 10
// baseline (speedup 1.0000x reference)
#include <cuda_runtime.h>

// Fixed shapes from reference setup_inputs
#define BB 4
#define NN 32
#define RR 64
#define HH 480
#define WW 640
#define HWSZ (HH * WW)              // 307200
#define PAIRS (BB * NN)             // 128
#define QUADS (HWSZ / 4)            // 76800 float4 per (b,n) plane

#define GROUPS 2                    // mask groups per batch
#define MPG 16                      // masks per group (depth reused 16x)
#define FAMS (BB * GROUPS)          // 8 (b,group) families
#define RANGES 74                   // quad-ranges per family
#define GRID (FAMS * RANGES)        // 592 = 148 SMs * 4 -> single wave

#define MARGIN_RANK 0.1f
#define MARGIN_OCC  0.3f
#define LAMBDA_OCC  1.5f
#define MIN_PIXELS  20.0f

// g_acc[2*p] = depth sum for pair p, g_acc[2*p+1] = pixel count.
// Zero at module load; last-arriving block re-zeros after use (graph-replay safe).
__device__ float    g_acc[2 * PAIRS];
__device__ unsigned g_arrive = 0;

__global__ __launch_bounds__(256, 4) void reldepth_fused_kernel(
    const float* __restrict__ depth,   // (B,1,H,W)
    const float* __restrict__ masks,   // (B,N,H,W)
    const int*   __restrict__ subj,    // (B,R)
    const int*   __restrict__ obj,     // (B,R)
    const int*   __restrict__ rel,     // (B,R)
    const float* __restrict__ conf,    // (B,R)
    float* __restrict__ out)
{
    const int t    = threadIdx.x;
    const int warp = t >> 5;
    const int lane = t & 31;

    // Decode block -> (family, range); family = (b, group)
    const int fam = blockIdx.x / RANGES;
    const int rr  = blockIdx.x % RANGES;
    const int b   = fam >> 1;          // fam / GROUPS
    const int g   = fam & 1;           // fam % GROUPS

    const int qs = (int)(((long long)rr       * QUADS) / RANGES);
    const int qe = (int)(((long long)(rr + 1) * QUADS) / RANGES);

    const float4* __restrict__ d4 = (const float4*)(depth + (size_t)b * HWSZ);
    const float4* __restrict__ m4 = (const float4*)(masks + (size_t)(b * NN + g * MPG) * HWSZ);

    float accd[MPG], accc[MPG];
    #pragma unroll
    for (int m = 0; m < MPG; m++) { accd[m] = 0.0f; accc[m] = 0.0f; }

    // ---- Streaming: 1 depth load reused by 16 mask streams (4 batches of 4) ----
    for (int i = qs + t; i < qe; i += 256) {
        float4 dv = __ldg(&d4[i]);
        #pragma unroll
        for (int mb = 0; mb < MPG / 4; mb++) {
            float4 mv[4];
            #pragma unroll
            for (int u = 0; u < 4; u++)
                mv[u] = __ldcs(&m4[(size_t)(mb * 4 + u) * QUADS + i]);
            #pragma unroll
            for (int u = 0; u < 4; u++) {
                const int m = mb * 4 + u;
                if (mv[u].x > 0.5f) { accc[m] += 1.0f; accd[m] += dv.x; }
                if (mv[u].y > 0.5f) { accc[m] += 1.0f; accd[m] += dv.y; }
                if (mv[u].z > 0.5f) { accc[m] += 1.0f; accd[m] += dv.z; }
                if (mv[u].w > 0.5f) { accc[m] += 1.0f; accd[m] += dv.w; }
            }
        }
    }

    // ---- Reduce 32 accumulators: warp shuffles, then cross-warp in smem ----
    __shared__ float s_red[8][2 * MPG];   // [warp][2*m + {0:sum,1:cnt}]
    #pragma unroll
    for (int m = 0; m < MPG; m++) {
        float d = accd[m], c = accc[m];
        #pragma unroll
        for (int off = 16; off > 0; off >>= 1) {
            d += __shfl_down_sync(0xFFFFFFFFu, d, off);
            c += __shfl_down_sync(0xFFFFFFFFu, c, off);
        }
        if (lane == 0) { s_red[warp][2 * m] = d; s_red[warp][2 * m + 1] = c; }
    }
    __syncthreads();

    if (t < 2 * MPG) {
        float v = 0.0f;
        #pragma unroll
        for (int w = 0; w < 8; w++) v += s_red[w][t];
        const int m     = t >> 1;
        const int which = t & 1;
        atomicAdd(&g_acc[2 * (b * NN + g * MPG + m) + which], v);
    }

    // ---- Arrival: last block runs the epilogue ----
    __shared__ bool s_last;
    __syncthreads();
    if (t == 0) {
        __threadfence();
        unsigned old = atomicAdd(&g_arrive, 1u);
        s_last = (old == GRID - 1);
        if (s_last) g_arrive = 0;
    }
    __syncthreads();
    if (!s_last) return;

    __threadfence();   // acquire all blocks' atomics

    __shared__ float s_dobj[PAIRS];
    __shared__ float s_cnt[PAIRS];

    if (t < PAIRS) {
        float D = g_acc[2 * t];
        float C = g_acc[2 * t + 1];
        s_dobj[t] = D / fmaxf(C, 1.0f);
        s_cnt[t]  = C;
        g_acc[2 * t]     = 0.0f;   // re-zero for next replay
        g_acc[2 * t + 1] = 0.0f;
    }
    __syncthreads();

    // 256 threads == B*R relations
    const int rb = t / RR;
    const int si = subj[t];
    const int oi = obj[t];
    const int rt = rel[t];
    const float cf = conf[t];

    const int ai = rb * NN + ((rt == 1) ? oi : si);
    const int bi = rb * NN + ((rt == 1) ? si : oi);

    const bool valid = (s_cnt[ai] >= MIN_PIXELS) && (s_cnt[bi] >= MIN_PIXELS);
    const float margin = (rt == 2) ? MARGIN_OCC : MARGIN_RANK;
    const float coeff  = (rt == 2) ? LAMBDA_OCC : 1.0f;
    const float viol = fmaxf(s_dobj[ai] - s_dobj[bi] + margin, 0.0f);

    float tot  = valid ? (coeff * cf * viol) : 0.0f;
    float vcnt = valid ? 1.0f : 0.0f;

    #pragma unroll
    for (int off = 16; off > 0; off >>= 1) {
        tot  += __shfl_down_sync(0xFFFFFFFFu, tot,  off);
        vcnt += __shfl_down_sync(0xFFFFFFFFu, vcnt, off);
    }
    __shared__ float s_t[8];
    __shared__ float s_v[8];
    if (lane == 0) { s_t[warp] = tot; s_v[warp] = vcnt; }
    __syncthreads();
    if (t == 0) {
        float T = 0.f, C = 0.f;
        #pragma unroll
        for (int w = 0; w < 8; w++) { T += s_t[w]; C += s_v[w]; }
        out[0] = (C > 0.0f) ? (T / fmaxf(C, 1.0f)) : 0.0f;
    }
}

extern "C" void kernel_launch(void* const* d_in, const int* in_sizes, int n_in,
                              void* d_out, int out_size)
{
    const float* depth = (const float*)d_in[0];
    const float* masks = (const float*)d_in[1];
    const int*   subj  = (const int*)d_in[2];
    const int*   obj   = (const int*)d_in[3];
    const int*   rel   = (const int*)d_in[4];
    const float* conf  = (const float*)d_in[5];
    float* out = (float*)d_out;

    reldepth_fused_kernel<<<GRID, 256>>>(depth, masks, subj, obj, rel, conf, out);
}

// round 12
// speedup vs baseline: 1.1232x; 1.1232x over previous
#include <cuda_runtime.h>

// Fixed shapes from reference setup_inputs
#define BB 4
#define NN 32
#define RR 64
#define HH 480
#define WW 640
#define HWSZ (HH * WW)              // 307200
#define PAIRS (BB * NN)             // 128
#define QUADS (HWSZ / 4)            // 76800 float4 per (b,n) plane

#define GROUPS 4                    // mask groups per batch
#define MPG 8                       // masks per group (R8 proven shape)
#define FAMS (BB * GROUPS)          // 16 (b,group) families
#define BLKS_PER_FAM 37
#define GRID (FAMS * BLKS_PER_FAM)  // 592 = 148 SMs * 4 -> single wave

#define TILE_QUADS 256              // one load-iteration per tile
#define TILES_PER_FAM (QUADS / TILE_QUADS)   // 300

#define MARGIN_RANK 0.1f
#define MARGIN_OCC  0.3f
#define LAMBDA_OCC  1.5f
#define MIN_PIXELS  20.0f

// g_acc[2*p] = depth sum for pair p, g_acc[2*p+1] = pixel count.
// All zero at module load; last-arriving block re-zeros/resets after use
// (arrival barrier guarantees all consumers are done), so graph replays are clean.
__device__ float    g_acc[2 * PAIRS];
__device__ unsigned g_ctr[FAMS];    // per-family work-stealing tile counters
__device__ unsigned g_arrive = 0;

__global__ __launch_bounds__(256, 4) void reldepth_fused_kernel(
    const float* __restrict__ depth,   // (B,1,H,W)
    const float* __restrict__ masks,   // (B,N,H,W)
    const int*   __restrict__ subj,    // (B,R)
    const int*   __restrict__ obj,     // (B,R)
    const int*   __restrict__ rel,     // (B,R)
    const float* __restrict__ conf,    // (B,R)
    float* __restrict__ out)
{
    const int t    = threadIdx.x;
    const int warp = t >> 5;
    const int lane = t & 31;

    // Static family assignment (accumulators live across stolen tiles)
    const int fam = blockIdx.x / BLKS_PER_FAM;
    const int b   = fam >> 2;          // fam / GROUPS
    const int g   = fam & 3;           // fam % GROUPS

    const float4* __restrict__ d4 = (const float4*)(depth + (size_t)b * HWSZ);
    const float4* __restrict__ m4 = (const float4*)(masks + (size_t)(b * NN + g * MPG) * HWSZ);

    float accd[MPG], accc[MPG];
    #pragma unroll
    for (int m = 0; m < MPG; m++) { accd[m] = 0.0f; accc[m] = 0.0f; }

    // ---- Streaming with intra-family work stealing (block-uniform tile ids) ----
    __shared__ int s_tile;
    for (;;) {
        if (t == 0) s_tile = (int)atomicAdd(&g_ctr[fam], 1u);
        __syncthreads();
        const int r = s_tile;
        __syncthreads();
        if (r >= TILES_PER_FAM) break;

        const int i = r * TILE_QUADS + t;
        float4 dv = __ldg(&d4[i]);
        float4 mv[MPG];
        #pragma unroll
        for (int m = 0; m < MPG; m++)
            mv[m] = __ldg(&m4[(size_t)m * QUADS + i]);
        #pragma unroll
        for (int m = 0; m < MPG; m++) {
            if (mv[m].x > 0.5f) { accc[m] += 1.0f; accd[m] += dv.x; }
            if (mv[m].y > 0.5f) { accc[m] += 1.0f; accd[m] += dv.y; }
            if (mv[m].z > 0.5f) { accc[m] += 1.0f; accd[m] += dv.z; }
            if (mv[m].w > 0.5f) { accc[m] += 1.0f; accd[m] += dv.w; }
        }
    }

    // ---- Reduce 16 accumulators: warp shuffles, then cross-warp in smem ----
    __shared__ float s_red[8][2 * MPG];   // [warp][2*m + {0:sum,1:cnt}]
    #pragma unroll
    for (int m = 0; m < MPG; m++) {
        float d = accd[m], c = accc[m];
        #pragma unroll
        for (int off = 16; off > 0; off >>= 1) {
            d += __shfl_down_sync(0xFFFFFFFFu, d, off);
            c += __shfl_down_sync(0xFFFFFFFFu, c, off);
        }
        if (lane == 0) { s_red[warp][2 * m] = d; s_red[warp][2 * m + 1] = c; }
    }
    __syncthreads();

    if (t < 2 * MPG) {
        float v = 0.0f;
        #pragma unroll
        for (int w = 0; w < 8; w++) v += s_red[w][t];
        const int m     = t >> 1;
        const int which = t & 1;
        atomicAdd(&g_acc[2 * (b * NN + g * MPG + m) + which], v);
    }

    // ---- Arrival: last block runs the epilogue ----
    __shared__ bool s_last;
    __syncthreads();
    if (t == 0) {
        __threadfence();
        unsigned old = atomicAdd(&g_arrive, 1u);
        s_last = (old == GRID - 1);
        if (s_last) g_arrive = 0;
    }
    __syncthreads();
    if (!s_last) return;

    __threadfence();   // acquire all blocks' atomics

    __shared__ float s_dobj[PAIRS];
    __shared__ float s_cnt[PAIRS];

    if (t < FAMS) g_ctr[t] = 0;    // reset stealing counters for next replay

    if (t < PAIRS) {
        float D = g_acc[2 * t];
        float C = g_acc[2 * t + 1];
        s_dobj[t] = D / fmaxf(C, 1.0f);
        s_cnt[t]  = C;
        g_acc[2 * t]     = 0.0f;   // re-zero for next replay
        g_acc[2 * t + 1] = 0.0f;
    }
    __syncthreads();

    // 256 threads == B*R relations
    const int rb = t / RR;
    const int si = subj[t];
    const int oi = obj[t];
    const int rt = rel[t];
    const float cf = conf[t];

    const int ai = rb * NN + ((rt == 1) ? oi : si);
    const int bi = rb * NN + ((rt == 1) ? si : oi);

    const bool valid = (s_cnt[ai] >= MIN_PIXELS) && (s_cnt[bi] >= MIN_PIXELS);
    const float margin = (rt == 2) ? MARGIN_OCC : MARGIN_RANK;
    const float coeff  = (rt == 2) ? LAMBDA_OCC : 1.0f;
    const float viol = fmaxf(s_dobj[ai] - s_dobj[bi] + margin, 0.0f);

    float tot  = valid ? (coeff * cf * viol) : 0.0f;
    float vcnt = valid ? 1.0f : 0.0f;

    #pragma unroll
    for (int off = 16; off > 0; off >>= 1) {
        tot  += __shfl_down_sync(0xFFFFFFFFu, tot,  off);
        vcnt += __shfl_down_sync(0xFFFFFFFFu, vcnt, off);
    }
    __shared__ float s_t[8];
    __shared__ float s_v[8];
    if (lane == 0) { s_t[warp] = tot; s_v[warp] = vcnt; }
    __syncthreads();
    if (t == 0) {
        float T = 0.f, C = 0.f;
        #pragma unroll
        for (int w = 0; w < 8; w++) { T += s_t[w]; C += s_v[w]; }
        out[0] = (C > 0.0f) ? (T / fmaxf(C, 1.0f)) : 0.0f;
    }
}

extern "C" void kernel_launch(void* const* d_in, const int* in_sizes, int n_in,
                              void* d_out, int out_size)
{
    const float* depth = (const float*)d_in[0];
    const float* masks = (const float*)d_in[1];
    const int*   subj  = (const int*)d_in[2];
    const int*   obj   = (const int*)d_in[3];
    const int*   rel   = (const int*)d_in[4];
    const float* conf  = (const float*)d_in[5];
    float* out = (float*)d_out;

    reldepth_fused_kernel<<<GRID, 256>>>(depth, masks, subj, obj, rel, conf, out);
}

// round 14
// speedup vs baseline: 1.2049x; 1.0727x over previous
#include <cuda_runtime.h>

// Fixed shapes from reference setup_inputs
#define BB 4
#define NN 32
#define RR 64
#define HH 480
#define WW 640
#define HWSZ (HH * WW)              // 307200
#define PAIRS (BB * NN)             // 128
#define QUADS (HWSZ / 4)            // 76800 float4 per (b,n) plane

#define GROUPS 8                    // mask groups per batch
#define MPG 4                       // masks per group (low reg pressure -> occ 6)
#define FAMS (BB * GROUPS)          // 32 (b,group) families
#define GRID 888                    // 148 SMs * 6 -> single wave at occ 6

#define TILE_QUADS 256              // one load-iteration per tile
#define TILES_PER_FAM (QUADS / TILE_QUADS)   // 300

#define MARGIN_RANK 0.1f
#define MARGIN_OCC  0.3f
#define LAMBDA_OCC  1.5f
#define MIN_PIXELS  20.0f

// g_acc[2*p] = depth sum for pair p, g_acc[2*p+1] = pixel count.
// All zero at module load; last-arriving block re-zeros/resets after use
// (arrival barrier guarantees all consumers are done), so graph replays are clean.
__device__ float    g_acc[2 * PAIRS];
__device__ unsigned g_ctr[FAMS];    // per-family work-stealing tile counters
__device__ unsigned g_arrive = 0;

__global__ __launch_bounds__(256, 6) void reldepth_fused_kernel(
    const float* __restrict__ depth,   // (B,1,H,W)
    const float* __restrict__ masks,   // (B,N,H,W)
    const int*   __restrict__ subj,    // (B,R)
    const int*   __restrict__ obj,     // (B,R)
    const int*   __restrict__ rel,     // (B,R)
    const float* __restrict__ conf,    // (B,R)
    float* __restrict__ out)
{
    const int t    = threadIdx.x;
    const int warp = t >> 5;
    const int lane = t & 31;

    // Round-robin family assignment; work stealing absorbs the ragged 888/32 split
    const int fam = blockIdx.x & (FAMS - 1);
    const int b   = fam >> 3;          // fam / GROUPS
    const int g   = fam & 7;           // fam % GROUPS

    const float4* __restrict__ d4 = (const float4*)(depth + (size_t)b * HWSZ);
    const float4* __restrict__ m4 = (const float4*)(masks + (size_t)(b * NN + g * MPG) * HWSZ);

    float accd[MPG], accc[MPG];
    #pragma unroll
    for (int m = 0; m < MPG; m++) { accd[m] = 0.0f; accc[m] = 0.0f; }

    // ---- Streaming with intra-family work stealing (block-uniform tile ids) ----
    __shared__ int s_tile;
    for (;;) {
        if (t == 0) s_tile = (int)atomicAdd(&g_ctr[fam], 1u);
        __syncthreads();
        const int r = s_tile;
        __syncthreads();
        if (r >= TILES_PER_FAM) break;

        const int i = r * TILE_QUADS + t;
        float4 dv = __ldg(&d4[i]);
        float4 mv[MPG];
        #pragma unroll
        for (int m = 0; m < MPG; m++)
            mv[m] = __ldg(&m4[(size_t)m * QUADS + i]);
        #pragma unroll
        for (int m = 0; m < MPG; m++) {
            if (mv[m].x > 0.5f) { accc[m] += 1.0f; accd[m] += dv.x; }
            if (mv[m].y > 0.5f) { accc[m] += 1.0f; accd[m] += dv.y; }
            if (mv[m].z > 0.5f) { accc[m] += 1.0f; accd[m] += dv.z; }
            if (mv[m].w > 0.5f) { accc[m] += 1.0f; accd[m] += dv.w; }
        }
    }

    // ---- Reduce 8 accumulators: warp shuffles, then cross-warp in smem ----
    __shared__ float s_red[8][2 * MPG];   // [warp][2*m + {0:sum,1:cnt}]
    #pragma unroll
    for (int m = 0; m < MPG; m++) {
        float d = accd[m], c = accc[m];
        #pragma unroll
        for (int off = 16; off > 0; off >>= 1) {
            d += __shfl_down_sync(0xFFFFFFFFu, d, off);
            c += __shfl_down_sync(0xFFFFFFFFu, c, off);
        }
        if (lane == 0) { s_red[warp][2 * m] = d; s_red[warp][2 * m + 1] = c; }
    }
    __syncthreads();

    if (t < 2 * MPG) {
        float v = 0.0f;
        #pragma unroll
        for (int w = 0; w < 8; w++) v += s_red[w][t];
        const int m     = t >> 1;
        const int which = t & 1;
        atomicAdd(&g_acc[2 * (b * NN + g * MPG + m) + which], v);
    }

    // ---- Arrival: last block runs the epilogue ----
    __shared__ bool s_last;
    __syncthreads();
    if (t == 0) {
        __threadfence();
        unsigned old = atomicAdd(&g_arrive, 1u);
        s_last = (old == GRID - 1);
        if (s_last) g_arrive = 0;
    }
    __syncthreads();
    if (!s_last) return;

    __threadfence();   // acquire all blocks' atomics

    __shared__ float s_dobj[PAIRS];
    __shared__ float s_cnt[PAIRS];

    if (t < FAMS) g_ctr[t] = 0;    // reset stealing counters for next replay

    if (t < PAIRS) {
        float D = g_acc[2 * t];
        float C = g_acc[2 * t + 1];
        s_dobj[t] = D / fmaxf(C, 1.0f);
        s_cnt[t]  = C;
        g_acc[2 * t]     = 0.0f;   // re-zero for next replay
        g_acc[2 * t + 1] = 0.0f;
    }
    __syncthreads();

    // 256 threads == B*R relations
    const int rb = t / RR;
    const int si = subj[t];
    const int oi = obj[t];
    const int rt = rel[t];
    const float cf = conf[t];

    const int ai = rb * NN + ((rt == 1) ? oi : si);
    const int bi = rb * NN + ((rt == 1) ? si : oi);

    const bool valid = (s_cnt[ai] >= MIN_PIXELS) && (s_cnt[bi] >= MIN_PIXELS);
    const float margin = (rt == 2) ? MARGIN_OCC : MARGIN_RANK;
    const float coeff  = (rt == 2) ? LAMBDA_OCC : 1.0f;
    const float viol = fmaxf(s_dobj[ai] - s_dobj[bi] + margin, 0.0f);

    float tot  = valid ? (coeff * cf * viol) : 0.0f;
    float vcnt = valid ? 1.0f : 0.0f;

    #pragma unroll
    for (int off = 16; off > 0; off >>= 1) {
        tot  += __shfl_down_sync(0xFFFFFFFFu, tot,  off);
        vcnt += __shfl_down_sync(0xFFFFFFFFu, vcnt, off);
    }
    __shared__ float s_t[8];
    __shared__ float s_v[8];
    if (lane == 0) { s_t[warp] = tot; s_v[warp] = vcnt; }
    __syncthreads();
    if (t == 0) {
        float T = 0.f, C = 0.f;
        #pragma unroll
        for (int w = 0; w < 8; w++) { T += s_t[w]; C += s_v[w]; }
        out[0] = (C > 0.0f) ? (T / fmaxf(C, 1.0f)) : 0.0f;
    }
}

extern "C" void kernel_launch(void* const* d_in, const int* in_sizes, int n_in,
                              void* d_out, int out_size)
{
    const float* depth = (const float*)d_in[0];
    const float* masks = (const float*)d_in[1];
    const int*   subj  = (const int*)d_in[2];
    const int*   obj   = (const int*)d_in[3];
    const int*   rel   = (const int*)d_in[4];
    const float* conf  = (const float*)d_in[5];
    float* out = (float*)d_out;

    reldepth_fused_kernel<<<GRID, 256>>>(depth, masks, subj, obj, rel, conf, out);
}